// round 8
// baseline (speedup 1.0000x reference)
#include <cuda_runtime.h>
#include <cuda_bf16.h>
#include <cstdint>

// ---------------------------------------------------------------------------
// RGBLambertianRendererWithVisibility — R8
//   Persistent TMA pipeline with warp-specialized producer:
//   288 threads = 8 compute warps + 1 producer warp; 3-stage ring (84KB),
//   full/empty mbarrier pairs, no __syncthreads in the tile loop.
//   Launch order [detect, shade, finalize, zero] puts shade at ncu launch #6.
// ---------------------------------------------------------------------------

#define MAX_RAYS 65536
#define SPB 16                                     // samples per tile
#define NSTAGE 3
#define STAGE_FLOATS (SPB * 192 * 2 + SPB * 64)    // 7168 floats = 28672 B
#define SMEM_BYTES (NSTAGE * STAGE_FLOATS * 4)     // 86016 B
#define NCOMPUTE_WARPS 8

__device__ float g_acc[MAX_RAYS * 4];
__device__ int   g_idx_is64;

// zero accumulators for the NEXT call (runs after finalize)
__global__ void zero_acc_kernel(int n4) {
    int i = blockIdx.x * blockDim.x + threadIdx.x;
    if (i < n4) g_acc[i] = 0.0f;
}

// int32 vs int64 ray_indices: inspect last 2048 of the first N int32 words
// (in-bounds for both layouts). Sorted nonneg indices are nonzero there for
// int32; int64 interleaves zero high words.
__global__ void detect_idx_kernel(const int* __restrict__ words, int n_words_safe) {
    int end   = n_words_safe;
    int start = end - 2048; if (start < 0) start = 0;
    int z = 0;
    for (int i = start + threadIdx.x; i < end; i += blockDim.x)
        z |= (words[i] == 0);
    int any = __syncthreads_or(z);
    if (threadIdx.x == 0) g_idx_is64 = any ? 1 : 0;
}

__device__ __forceinline__ uint32_t smem_u32(const void* p) {
    uint32_t a;
    asm("{ .reg .u64 t; cvta.to.shared.u64 t, %1; cvt.u32.u64 %0, t; }"
        : "=r"(a) : "l"(p));
    return a;
}

__device__ __forceinline__ void mbar_wait(uint32_t mbar, uint32_t parity) {
    uint32_t done;
    asm volatile(
        "{\n\t"
        ".reg .pred p;\n\t"
        "mbarrier.try_wait.parity.acquire.cta.shared::cta.b64 p, [%1], %2;\n\t"
        "selp.b32 %0, 1, 0, p;\n\t"
        "}" : "=r"(done) : "r"(mbar), "r"(parity) : "memory");
    if (!done) {
        asm volatile(
            "{\n\t"
            ".reg .pred P1;\n\t"
            "WAIT_LOOP_%=:\n\t"
            "mbarrier.try_wait.parity.acquire.cta.shared::cta.b64 P1, [%0], %1, 0x989680;\n\t"
            "@P1 bra.uni WAIT_DONE_%=;\n\t"
            "bra.uni WAIT_LOOP_%=;\n\t"
            "WAIT_DONE_%=:\n\t"
            "}" :: "r"(mbar), "r"(parity) : "memory");
    }
}

__device__ __forceinline__ void issue_tile(
        float* stage_base, uint32_t full_mbar,
        const float* ldir, const float* lcol, const float* vis,
        int tile_base, int nloc) {
    unsigned db = (unsigned)nloc * 768u;
    unsigned vb = (unsigned)nloc * 256u;
    asm volatile("mbarrier.arrive.expect_tx.shared.b64 _, [%0], %1;"
                 :: "r"(full_mbar), "r"(db * 2u + vb) : "memory");
    asm volatile(
        "cp.async.bulk.shared::cta.global.mbarrier::complete_tx::bytes [%0], [%1], %2, [%3];"
        :: "r"(smem_u32(stage_base)), "l"(ldir + (size_t)tile_base * 192),
           "r"(db), "r"(full_mbar) : "memory");
    asm volatile(
        "cp.async.bulk.shared::cta.global.mbarrier::complete_tx::bytes [%0], [%1], %2, [%3];"
        :: "r"(smem_u32(stage_base + SPB * 192)), "l"(lcol + (size_t)tile_base * 192),
           "r"(db), "r"(full_mbar) : "memory");
    asm volatile(
        "cp.async.bulk.shared::cta.global.mbarrier::complete_tx::bytes [%0], [%1], %2, [%3];"
        :: "r"(smem_u32(stage_base + SPB * 384)), "l"(vis + (size_t)tile_base * 64),
           "r"(vb), "r"(full_mbar) : "memory");
}

// --- persistent pipelined shade (L == 64) -----------------------------------
__global__ __launch_bounds__(288) void shade_pipe_kernel(
        const float* __restrict__ albedos,
        const float* __restrict__ normals,
        const float* __restrict__ ldir,
        const float* __restrict__ lcol,
        const float* __restrict__ vis,
        const float* __restrict__ weights,
        const void*  __restrict__ ray_idx,
        int N, int ntiles) {
    extern __shared__ __align__(16) float smem[];
    __shared__ __align__(8) unsigned long long sm_full[NSTAGE];
    __shared__ __align__(8) unsigned long long sm_empty[NSTAGE];

    int tid  = threadIdx.x;
    int warp = tid >> 5;
    int lane = tid & 31;

    if (tid == 0) {
        #pragma unroll
        for (int s = 0; s < NSTAGE; ++s) {
            asm volatile("mbarrier.init.shared.b64 [%0], 1;"
                         :: "r"(smem_u32(&sm_full[s])) : "memory");
            asm volatile("mbarrier.init.shared.b64 [%0], %1;"
                         :: "r"(smem_u32(&sm_empty[s])), "r"(NCOMPUTE_WARPS) : "memory");
        }
    }
    __syncthreads();

    int my_tiles = 0;
    if (blockIdx.x < (unsigned)ntiles)
        my_tiles = (ntiles - 1 - blockIdx.x) / gridDim.x + 1;
    if (my_tiles == 0) return;

    if (warp == NCOMPUTE_WARPS) {
        // ---------------- producer warp ----------------
        if (lane == 0) {
            int stage = 0, phase = 1;          // first NSTAGE empty-waits pass
            for (int j = 0; j < my_tiles; ++j) {
                mbar_wait(smem_u32(&sm_empty[stage]), (uint32_t)phase);
                asm volatile("fence.proxy.async.shared::cta;" ::: "memory");
                int t  = blockIdx.x + j * gridDim.x;
                int tb = t * SPB;
                int nloc = N - tb; if (nloc > SPB) nloc = SPB;
                issue_tile(smem + stage * STAGE_FLOATS,
                           smem_u32(&sm_full[stage]),
                           ldir, lcol, vis, tb, nloc);
                if (++stage == NSTAGE) { stage = 0; phase ^= 1; }
            }
        }
        return;
    }

    // ---------------- compute warps ----------------
    int half = lane >> 4;
    int sub  = lane & 15;
    int sl   = warp * 2 + half;        // local sample 0..15

    int stage = 0, phase = 0;
    for (int j = 0; j < my_tiles; ++j) {
        int base = (blockIdx.x + j * gridDim.x) * SPB;

        mbar_wait(smem_u32(&sm_full[stage]), (uint32_t)phase);

        float* stg = smem + stage * STAGE_FLOATS;
        int s    = base + sl;
        bool live = (s < N);
        int sll  = live ? sl : 0;

        const float4* sd = (const float4*)(stg + sll * 192);
        const float4* sc = (const float4*)(stg + SPB * 192 + sll * 192);
        const float4* sv = (const float4*)(stg + SPB * 384 + sll * 64);

        float4 d0 = sd[sub * 3 + 0];
        float4 d1 = sd[sub * 3 + 1];
        float4 d2 = sd[sub * 3 + 2];
        float4 c0 = sc[sub * 3 + 0];
        float4 c1 = sc[sub * 3 + 1];
        float4 c2 = sc[sub * 3 + 2];
        float4 v  = sv[sub];

        // reads done -> release this stage (one arrive per warp)
        __syncwarp();
        if (lane == 0)
            asm volatile("mbarrier.arrive.release.cta.shared::cta.b64 _, [%0];"
                         :: "r"(smem_u32(&sm_empty[stage])) : "memory");

        int scl = live ? s : 0;
        float nx = normals[scl * 3 + 0];
        float ny = normals[scl * 3 + 1];
        float nz = normals[scl * 3 + 2];

        float t0 = fmaf(nx, d0.x, fmaf(ny, d0.y, nz * d0.z));
        float t1 = fmaf(nx, d0.w, fmaf(ny, d1.x, nz * d1.y));
        float t2 = fmaf(nx, d1.z, fmaf(ny, d1.w, nz * d2.x));
        float t3 = fmaf(nx, d2.y, fmaf(ny, d2.z, nz * d2.w));

        int cnt = (t0 > 0.f) + (t1 > 0.f) + (t2 > 0.f) + (t3 > 0.f);

        t0 = fminf(fmaxf(t0, 0.f), 1.f) * v.x;
        t1 = fminf(fmaxf(t1, 0.f), 1.f) * v.y;
        t2 = fminf(fmaxf(t2, 0.f), 1.f) * v.z;
        t3 = fminf(fmaxf(t3, 0.f), 1.f) * v.w;

        float s0 = fmaf(t0, c0.x, fmaf(t1, c0.w, fmaf(t2, c1.z, t3 * c2.y)));
        float s1 = fmaf(t0, c0.y, fmaf(t1, c1.x, fmaf(t2, c1.w, t3 * c2.z)));
        float s2 = fmaf(t0, c0.z, fmaf(t1, c1.y, fmaf(t2, c2.x, t3 * c2.w)));

        #pragma unroll
        for (int off = 8; off; off >>= 1) {
            s0  += __shfl_xor_sync(0xFFFFFFFFu, s0,  off);
            s1  += __shfl_xor_sync(0xFFFFFFFFu, s1,  off);
            s2  += __shfl_xor_sync(0xFFFFFFFFu, s2,  off);
            cnt += __shfl_xor_sync(0xFFFFFFFFu, cnt, off);
        }

        if (sub == 0 && live) {
            float c   = (cnt > 0) ? (float)cnt : 1.0f;
            float inv = 1.0f / c;
            float w   = weights[s];
            int r;
            if (g_idx_is64) r = (int)((const long long*)ray_idx)[s];
            else            r = ((const int*)ray_idx)[s];
            float a0 = albedos[s * 3 + 0];
            float a1 = albedos[s * 3 + 1];
            float a2 = albedos[s * 3 + 2];
            atomicAdd(&g_acc[r * 4 + 0], w * a0 * s0 * inv);
            atomicAdd(&g_acc[r * 4 + 1], w * a1 * s1 * inv);
            atomicAdd(&g_acc[r * 4 + 2], w * a2 * s2 * inv);
            atomicAdd(&g_acc[r * 4 + 3], w);
        }

        if (++stage == NSTAGE) { stage = 0; phase ^= 1; }
    }
}

__global__ void finalize_kernel(const float* __restrict__ bg,
                                float* __restrict__ out, int R) {
    int r = blockIdx.x * blockDim.x + threadIdx.x;
    if (r >= R) return;
    float aw = g_acc[r * 4 + 3];
    float one_m = 1.0f - aw;
    #pragma unroll
    for (int c = 0; c < 3; ++c) {
        float x = g_acc[r * 4 + c] + bg[r * 3 + c] * one_m;
        float safe = fmaxf(x, 1e-8f);
        float y = (x <= 0.0031308f) ? (12.92f * x)
                                    : (1.055f * powf(safe, 1.0f / 2.4f) - 0.055f);
        out[r * 3 + c] = y;
    }
}

// Fallback for L != 64
__global__ void shade_kernel_generic(
        const float* __restrict__ albedos,
        const float* __restrict__ normals,
        const float* __restrict__ ldir,
        const float* __restrict__ lcol,
        const float* __restrict__ vis,
        const float* __restrict__ weights,
        const void*  __restrict__ ray_idx,
        int N, int L) {
    int gwarp = (blockIdx.x * blockDim.x + threadIdx.x) >> 5;
    int lane  = threadIdx.x & 31;
    if (gwarp >= N) return;
    float nx = normals[gwarp * 3 + 0];
    float ny = normals[gwarp * 3 + 1];
    float nz = normals[gwarp * 3 + 2];
    const float* ldp = ldir + (size_t)gwarp * L * 3;
    const float* lcp = lcol + (size_t)gwarp * L * 3;
    const float* vp  = vis  + (size_t)gwarp * L;
    float s0 = 0.f, s1 = 0.f, s2 = 0.f;
    int cnt = 0;
    for (int j = lane; j < L; j += 32) {
        float dx = ldp[j * 3 + 0], dy = ldp[j * 3 + 1], dz = ldp[j * 3 + 2];
        float d  = fmaf(nx, dx, fmaf(ny, dy, nz * dz));
        cnt += (d > 0.f) ? 1 : 0;
        d = fminf(fmaxf(d, 0.f), 1.f);
        float dv = d * vp[j];
        s0 = fmaf(dv, lcp[j * 3 + 0], s0);
        s1 = fmaf(dv, lcp[j * 3 + 1], s1);
        s2 = fmaf(dv, lcp[j * 3 + 2], s2);
    }
    #pragma unroll
    for (int off = 16; off; off >>= 1) {
        s0  += __shfl_xor_sync(0xFFFFFFFFu, s0,  off);
        s1  += __shfl_xor_sync(0xFFFFFFFFu, s1,  off);
        s2  += __shfl_xor_sync(0xFFFFFFFFu, s2,  off);
        cnt += __shfl_xor_sync(0xFFFFFFFFu, cnt, off);
    }
    if (lane == 0) {
        float c   = (cnt > 0) ? (float)cnt : 1.0f;
        float inv = 1.0f / c;
        float w   = weights[gwarp];
        int r;
        if (g_idx_is64) r = (int)((const long long*)ray_idx)[gwarp];
        else            r = ((const int*)ray_idx)[gwarp];
        atomicAdd(&g_acc[r * 4 + 0], w * albedos[gwarp * 3 + 0] * s0 * inv);
        atomicAdd(&g_acc[r * 4 + 1], w * albedos[gwarp * 3 + 1] * s1 * inv);
        atomicAdd(&g_acc[r * 4 + 2], w * albedos[gwarp * 3 + 2] * s2 * inv);
        atomicAdd(&g_acc[r * 4 + 3], w);
    }
}

extern "C" void kernel_launch(void* const* d_in, const int* in_sizes, int n_in,
                              void* d_out, int out_size) {
    const float* albedos = (const float*)d_in[0];
    const float* normals = (const float*)d_in[1];
    const float* ldir    = (const float*)d_in[2];
    const float* lcol    = (const float*)d_in[3];
    const float* vis     = (const float*)d_in[4];
    const float* bg      = (const float*)d_in[5];
    const float* weights = (const float*)d_in[6];
    const void*  ray_idx = (const void*) d_in[7];
    float* out = (float*)d_out;

    int N = in_sizes[0] / 3;
    int L = (N > 0) ? in_sizes[2] / (N * 3) : 1;
    int R = out_size / 3;
    if (R > MAX_RAYS) R = MAX_RAYS;
    int n4 = R * 4;

    // g_acc is zero at module load (call 1) and re-zeroed at the END of
    // every call, so shade can run immediately after detect.
    detect_idx_kernel<<<1, 1024>>>((const int*)ray_idx, in_sizes[7]);

    if (L == 64) {
        static int smem_set = 0;
        if (!smem_set) {
            cudaFuncSetAttribute(shade_pipe_kernel,
                                 cudaFuncAttributeMaxDynamicSharedMemorySize,
                                 SMEM_BYTES);
            smem_set = 1;
        }
        int ntiles = (N + SPB - 1) / SPB;
        int grid = 296;
        if (grid > ntiles) grid = ntiles;
        shade_pipe_kernel<<<grid, 288, SMEM_BYTES>>>(
            albedos, normals, ldir, lcol, vis, weights, ray_idx, N, ntiles);
    } else {
        int blocks = (N + 7) / 8;
        shade_kernel_generic<<<blocks, 256>>>(
            albedos, normals, ldir, lcol, vis, weights, ray_idx, N, L);
    }

    finalize_kernel<<<(R + 255) / 256, 256>>>(bg, out, R);

    // zero for the NEXT call (finalize has already consumed g_acc)
    zero_acc_kernel<<<(n4 + 255) / 256, 256>>>(n4);
}

// round 9
// speedup vs baseline: 1.1723x; 1.1723x over previous
#include <cuda_runtime.h>
#include <cuda_bf16.h>
#include <cstdint>

// ---------------------------------------------------------------------------
// RGBLambertianRendererWithVisibility — R9
//   Persistent TMA pipeline, SPB=32, 1 CTA/SM (grid=148), 3x57KB stages.
//   ALL per-sample data (dir,col,vis,normals,albedos,weights,ray_idx) is
//   TMA-staged; consumers touch only smem + accumulator atomics.
//   Launches: [detect, shade, finalize(+zero)].
// ---------------------------------------------------------------------------

#define MAX_RAYS 65536
#define SPB 32
#define NSTAGE 3
#define NCW 16                         // compute warps
// stage layout (floats)
#define OFF_DIR  0
#define OFF_COL  (SPB * 192)                    // 6144
#define OFF_VIS  (SPB * 384)                    // 12288
#define OFF_NRM  (OFF_VIS + SPB * 64)           // 14336
#define OFF_ALB  (OFF_NRM + SPB * 3)            // 14432
#define OFF_WGT  (OFF_ALB + SPB * 3)            // 14528
#define OFF_IDX  (OFF_WGT + SPB)                // 14560
#define STAGE_FLOATS (OFF_IDX + SPB * 2)        // 14624 floats = 58496 B
#define SMEM_BYTES (NSTAGE * STAGE_FLOATS * 4)  // 175488 B

__device__ float g_acc[MAX_RAYS * 4];
__device__ int   g_idx_is64;

// int32 vs int64 ray_indices: inspect last 2048 of the first N int32 words
// (in-bounds for both layouts). Sorted nonneg indices are nonzero there for
// int32; int64 interleaves zero high words.
__global__ void detect_idx_kernel(const int* __restrict__ words, int n_words_safe) {
    int end   = n_words_safe;
    int start = end - 2048; if (start < 0) start = 0;
    int z = 0;
    for (int i = start + threadIdx.x; i < end; i += blockDim.x)
        z |= (words[i] == 0);
    int any = __syncthreads_or(z);
    if (threadIdx.x == 0) g_idx_is64 = any ? 1 : 0;
}

__device__ __forceinline__ uint32_t smem_u32(const void* p) {
    uint32_t a;
    asm("{ .reg .u64 t; cvta.to.shared.u64 t, %1; cvt.u32.u64 %0, t; }"
        : "=r"(a) : "l"(p));
    return a;
}

__device__ __forceinline__ void mbar_wait(uint32_t mbar, uint32_t parity) {
    uint32_t done;
    asm volatile(
        "{\n\t"
        ".reg .pred p;\n\t"
        "mbarrier.try_wait.parity.acquire.cta.shared::cta.b64 p, [%1], %2;\n\t"
        "selp.b32 %0, 1, 0, p;\n\t"
        "}" : "=r"(done) : "r"(mbar), "r"(parity) : "memory");
    if (!done) {
        asm volatile(
            "{\n\t"
            ".reg .pred P1;\n\t"
            "WAIT_LOOP_%=:\n\t"
            "mbarrier.try_wait.parity.acquire.cta.shared::cta.b64 P1, [%0], %1, 0x989680;\n\t"
            "@P1 bra.uni WAIT_DONE_%=;\n\t"
            "bra.uni WAIT_LOOP_%=;\n\t"
            "WAIT_DONE_%=:\n\t"
            "}" :: "r"(mbar), "r"(parity) : "memory");
    }
}

__device__ __forceinline__ void bulk_cp(uint32_t dst, const void* src,
                                        unsigned bytes, uint32_t mbar) {
    asm volatile(
        "cp.async.bulk.shared::cta.global.mbarrier::complete_tx::bytes [%0], [%1], %2, [%3];"
        :: "r"(dst), "l"(src), "r"(bytes), "r"(mbar) : "memory");
}

// --- persistent pipelined shade (L == 64) -----------------------------------
__global__ __launch_bounds__(544) void shade_pipe_kernel(
        const float* __restrict__ albedos,
        const float* __restrict__ normals,
        const float* __restrict__ ldir,
        const float* __restrict__ lcol,
        const float* __restrict__ vis,
        const float* __restrict__ weights,
        const void*  __restrict__ ray_idx,
        int N, int ntiles) {
    extern __shared__ __align__(16) float smem[];
    __shared__ __align__(8) unsigned long long sm_full[NSTAGE];
    __shared__ __align__(8) unsigned long long sm_empty[NSTAGE];

    int tid  = threadIdx.x;
    int warp = tid >> 5;
    int lane = tid & 31;

    if (tid == 0) {
        #pragma unroll
        for (int s = 0; s < NSTAGE; ++s) {
            asm volatile("mbarrier.init.shared.b64 [%0], 1;"
                         :: "r"(smem_u32(&sm_full[s])) : "memory");
            asm volatile("mbarrier.init.shared.b64 [%0], %1;"
                         :: "r"(smem_u32(&sm_empty[s])), "r"(NCW) : "memory");
        }
    }
    __syncthreads();

    int my_tiles = 0;
    if (blockIdx.x < (unsigned)ntiles)
        my_tiles = (ntiles - 1 - (int)blockIdx.x) / gridDim.x + 1;
    if (my_tiles == 0) return;

    int is64 = g_idx_is64;

    if (warp == NCW) {
        // ---------------- producer warp ----------------
        if (lane == 0) {
            int stage = 0, phase = 1;
            for (int j = 0; j < my_tiles; ++j) {
                mbar_wait(smem_u32(&sm_empty[stage]), (uint32_t)phase);
                asm volatile("fence.proxy.async.shared::cta;" ::: "memory");
                int t  = (int)blockIdx.x + j * gridDim.x;
                int tb = t * SPB;
                int nloc = N - tb; if (nloc > SPB) nloc = SPB;
                bool aux = (nloc % 4) == 0;       // aux sizes 16B-multiples

                float* stg = smem + stage * STAGE_FLOATS;
                uint32_t mb = smem_u32(&sm_full[stage]);
                unsigned db = (unsigned)nloc * 768u;
                unsigned vb = (unsigned)nloc * 256u;
                unsigned ab = aux ? ((unsigned)nloc * (12u + 12u + 4u)
                                     + (unsigned)nloc * (is64 ? 8u : 4u)) : 0u;
                asm volatile("mbarrier.arrive.expect_tx.shared.b64 _, [%0], %1;"
                             :: "r"(mb), "r"(db * 2u + vb + ab) : "memory");
                bulk_cp(smem_u32(stg + OFF_DIR), ldir + (size_t)tb * 192, db, mb);
                bulk_cp(smem_u32(stg + OFF_COL), lcol + (size_t)tb * 192, db, mb);
                bulk_cp(smem_u32(stg + OFF_VIS), vis  + (size_t)tb * 64,  vb, mb);
                if (aux) {
                    bulk_cp(smem_u32(stg + OFF_NRM), normals + (size_t)tb * 3,
                            (unsigned)nloc * 12u, mb);
                    bulk_cp(smem_u32(stg + OFF_ALB), albedos + (size_t)tb * 3,
                            (unsigned)nloc * 12u, mb);
                    bulk_cp(smem_u32(stg + OFF_WGT), weights + (size_t)tb,
                            (unsigned)nloc * 4u, mb);
                    if (is64)
                        bulk_cp(smem_u32(stg + OFF_IDX),
                                (const long long*)ray_idx + tb,
                                (unsigned)nloc * 8u, mb);
                    else
                        bulk_cp(smem_u32(stg + OFF_IDX),
                                (const int*)ray_idx + tb,
                                (unsigned)nloc * 4u, mb);
                }
                if (++stage == NSTAGE) { stage = 0; phase ^= 1; }
            }
        }
        return;
    }

    // ---------------- compute warps (warp 0..15) ----------------
    int half = lane >> 4;
    int sub  = lane & 15;
    int sl   = warp * 2 + half;        // local sample 0..31

    int stage = 0, phase = 0;
    for (int j = 0; j < my_tiles; ++j) {
        int base = ((int)blockIdx.x + j * gridDim.x) * SPB;
        int nloc = N - base; if (nloc > SPB) nloc = SPB;
        bool aux = (nloc % 4) == 0;

        mbar_wait(smem_u32(&sm_full[stage]), (uint32_t)phase);

        float* stg = smem + stage * STAGE_FLOATS;
        int s    = base + sl;
        bool live = (s < N);
        int sll  = live ? sl : 0;

        const float4* sd = (const float4*)(stg + OFF_DIR + sll * 192);
        const float4* sc = (const float4*)(stg + OFF_COL + sll * 192);
        const float4* sv = (const float4*)(stg + OFF_VIS + sll * 64);

        float4 d0 = sd[sub * 3 + 0];
        float4 d1 = sd[sub * 3 + 1];
        float4 d2 = sd[sub * 3 + 2];
        float4 c0 = sc[sub * 3 + 0];
        float4 c1 = sc[sub * 3 + 1];
        float4 c2 = sc[sub * 3 + 2];
        float4 v  = sv[sub];

        float nx, ny, nz;
        if (aux) {
            nx = stg[OFF_NRM + sll * 3 + 0];
            ny = stg[OFF_NRM + sll * 3 + 1];
            nz = stg[OFF_NRM + sll * 3 + 2];
        } else {
            int scl = live ? s : 0;
            nx = normals[scl * 3 + 0];
            ny = normals[scl * 3 + 1];
            nz = normals[scl * 3 + 2];
        }

        // per-sample aux for the atomic lane (read from smem before release)
        float w = 0.f, a0 = 0.f, a1 = 0.f, a2 = 0.f;
        int r = 0;
        if (sub == 0 && live) {
            if (aux) {
                w  = stg[OFF_WGT + sl];
                a0 = stg[OFF_ALB + sl * 3 + 0];
                a1 = stg[OFF_ALB + sl * 3 + 1];
                a2 = stg[OFF_ALB + sl * 3 + 2];
                if (is64) r = (int)((const long long*)(stg + OFF_IDX))[sl];
                else      r = ((const int*)(stg + OFF_IDX))[sl];
            } else {
                w  = weights[s];
                a0 = albedos[s * 3 + 0];
                a1 = albedos[s * 3 + 1];
                a2 = albedos[s * 3 + 2];
                if (is64) r = (int)((const long long*)ray_idx)[s];
                else      r = ((const int*)ray_idx)[s];
            }
        }

        // all stage reads done -> release stage (one arrive per warp)
        __syncwarp();
        if (lane == 0)
            asm volatile("mbarrier.arrive.release.cta.shared::cta.b64 _, [%0];"
                         :: "r"(smem_u32(&sm_empty[stage])) : "memory");

        float t0 = fmaf(nx, d0.x, fmaf(ny, d0.y, nz * d0.z));
        float t1 = fmaf(nx, d0.w, fmaf(ny, d1.x, nz * d1.y));
        float t2 = fmaf(nx, d1.z, fmaf(ny, d1.w, nz * d2.x));
        float t3 = fmaf(nx, d2.y, fmaf(ny, d2.z, nz * d2.w));

        int cnt = (t0 > 0.f) + (t1 > 0.f) + (t2 > 0.f) + (t3 > 0.f);

        t0 = fminf(fmaxf(t0, 0.f), 1.f) * v.x;
        t1 = fminf(fmaxf(t1, 0.f), 1.f) * v.y;
        t2 = fminf(fmaxf(t2, 0.f), 1.f) * v.z;
        t3 = fminf(fmaxf(t3, 0.f), 1.f) * v.w;

        float s0 = fmaf(t0, c0.x, fmaf(t1, c0.w, fmaf(t2, c1.z, t3 * c2.y)));
        float s1 = fmaf(t0, c0.y, fmaf(t1, c1.x, fmaf(t2, c1.w, t3 * c2.z)));
        float s2 = fmaf(t0, c0.z, fmaf(t1, c1.y, fmaf(t2, c2.x, t3 * c2.w)));

        #pragma unroll
        for (int off = 8; off; off >>= 1) {
            s0  += __shfl_xor_sync(0xFFFFFFFFu, s0,  off);
            s1  += __shfl_xor_sync(0xFFFFFFFFu, s1,  off);
            s2  += __shfl_xor_sync(0xFFFFFFFFu, s2,  off);
            cnt += __shfl_xor_sync(0xFFFFFFFFu, cnt, off);
        }

        if (sub == 0 && live) {
            float c   = (cnt > 0) ? (float)cnt : 1.0f;
            float inv = 1.0f / c;
            atomicAdd(&g_acc[r * 4 + 0], w * a0 * s0 * inv);
            atomicAdd(&g_acc[r * 4 + 1], w * a1 * s1 * inv);
            atomicAdd(&g_acc[r * 4 + 2], w * a2 * s2 * inv);
            atomicAdd(&g_acc[r * 4 + 3], w);
        }

        if (++stage == NSTAGE) { stage = 0; phase ^= 1; }
    }
}

// finalize: blend + sRGB, then zero g_acc for the NEXT call.
__global__ void finalize_kernel(const float* __restrict__ bg,
                                float* __restrict__ out, int R) {
    int r = blockIdx.x * blockDim.x + threadIdx.x;
    if (r >= R) return;
    float aw = g_acc[r * 4 + 3];
    float x0 = g_acc[r * 4 + 0];
    float x1 = g_acc[r * 4 + 1];
    float x2 = g_acc[r * 4 + 2];
    float one_m = 1.0f - aw;
    float xr[3] = { x0 + bg[r * 3 + 0] * one_m,
                    x1 + bg[r * 3 + 1] * one_m,
                    x2 + bg[r * 3 + 2] * one_m };
    #pragma unroll
    for (int c = 0; c < 3; ++c) {
        float x = xr[c];
        float safe = fmaxf(x, 1e-8f);
        float y = (x <= 0.0031308f) ? (12.92f * x)
                                    : (1.055f * powf(safe, 1.0f / 2.4f) - 0.055f);
        out[r * 3 + c] = y;
    }
    g_acc[r * 4 + 0] = 0.0f;
    g_acc[r * 4 + 1] = 0.0f;
    g_acc[r * 4 + 2] = 0.0f;
    g_acc[r * 4 + 3] = 0.0f;
}

// Fallback for L != 64
__global__ void shade_kernel_generic(
        const float* __restrict__ albedos,
        const float* __restrict__ normals,
        const float* __restrict__ ldir,
        const float* __restrict__ lcol,
        const float* __restrict__ vis,
        const float* __restrict__ weights,
        const void*  __restrict__ ray_idx,
        int N, int L) {
    int gwarp = (blockIdx.x * blockDim.x + threadIdx.x) >> 5;
    int lane  = threadIdx.x & 31;
    if (gwarp >= N) return;
    float nx = normals[gwarp * 3 + 0];
    float ny = normals[gwarp * 3 + 1];
    float nz = normals[gwarp * 3 + 2];
    const float* ldp = ldir + (size_t)gwarp * L * 3;
    const float* lcp = lcol + (size_t)gwarp * L * 3;
    const float* vp  = vis  + (size_t)gwarp * L;
    float s0 = 0.f, s1 = 0.f, s2 = 0.f;
    int cnt = 0;
    for (int j = lane; j < L; j += 32) {
        float dx = ldp[j * 3 + 0], dy = ldp[j * 3 + 1], dz = ldp[j * 3 + 2];
        float d  = fmaf(nx, dx, fmaf(ny, dy, nz * dz));
        cnt += (d > 0.f) ? 1 : 0;
        d = fminf(fmaxf(d, 0.f), 1.f);
        float dv = d * vp[j];
        s0 = fmaf(dv, lcp[j * 3 + 0], s0);
        s1 = fmaf(dv, lcp[j * 3 + 1], s1);
        s2 = fmaf(dv, lcp[j * 3 + 2], s2);
    }
    #pragma unroll
    for (int off = 16; off; off >>= 1) {
        s0  += __shfl_xor_sync(0xFFFFFFFFu, s0,  off);
        s1  += __shfl_xor_sync(0xFFFFFFFFu, s1,  off);
        s2  += __shfl_xor_sync(0xFFFFFFFFu, s2,  off);
        cnt += __shfl_xor_sync(0xFFFFFFFFu, cnt, off);
    }
    if (lane == 0) {
        float c   = (cnt > 0) ? (float)cnt : 1.0f;
        float inv = 1.0f / c;
        float w   = weights[gwarp];
        int r;
        if (g_idx_is64) r = (int)((const long long*)ray_idx)[gwarp];
        else            r = ((const int*)ray_idx)[gwarp];
        atomicAdd(&g_acc[r * 4 + 0], w * albedos[gwarp * 3 + 0] * s0 * inv);
        atomicAdd(&g_acc[r * 4 + 1], w * albedos[gwarp * 3 + 1] * s1 * inv);
        atomicAdd(&g_acc[r * 4 + 2], w * albedos[gwarp * 3 + 2] * s2 * inv);
        atomicAdd(&g_acc[r * 4 + 3], w);
    }
}

extern "C" void kernel_launch(void* const* d_in, const int* in_sizes, int n_in,
                              void* d_out, int out_size) {
    const float* albedos = (const float*)d_in[0];
    const float* normals = (const float*)d_in[1];
    const float* ldir    = (const float*)d_in[2];
    const float* lcol    = (const float*)d_in[3];
    const float* vis     = (const float*)d_in[4];
    const float* bg      = (const float*)d_in[5];
    const float* weights = (const float*)d_in[6];
    const void*  ray_idx = (const void*) d_in[7];
    float* out = (float*)d_out;

    int N = in_sizes[0] / 3;
    int L = (N > 0) ? in_sizes[2] / (N * 3) : 1;
    int R = out_size / 3;
    if (R > MAX_RAYS) R = MAX_RAYS;

    // g_acc zero at load (call 1); finalize re-zeros it each call.
    detect_idx_kernel<<<1, 1024>>>((const int*)ray_idx, in_sizes[7]);

    if (L == 64) {
        static int smem_set = 0;
        if (!smem_set) {
            cudaFuncSetAttribute(shade_pipe_kernel,
                                 cudaFuncAttributeMaxDynamicSharedMemorySize,
                                 SMEM_BYTES);
            smem_set = 1;
        }
        int ntiles = (N + SPB - 1) / SPB;
        int grid = 148;                 // 1 CTA per SM
        if (grid > ntiles) grid = ntiles;
        shade_pipe_kernel<<<grid, 544, SMEM_BYTES>>>(
            albedos, normals, ldir, lcol, vis, weights, ray_idx, N, ntiles);
    } else {
        int blocks = (N + 7) / 8;
        shade_kernel_generic<<<blocks, 256>>>(
            albedos, normals, ldir, lcol, vis, weights, ray_idx, N, L);
    }

    finalize_kernel<<<(R + 255) / 256, 256>>>(bg, out, R);
}